// round 3
// baseline (speedup 1.0000x reference)
#include <cuda_runtime.h>

#define FULLMASK 0xffffffffu

constexpr int Nn = 8;
constexpr int Cc = 128;
constexpr int Hh = 160;
constexpr int Ww = 160;
constexpr int HWC = Hh * Ww * Cc;        // per-image NHWC stride
constexpr int TOT = Nn * HWC;            // 26,214,400

// Ping-pong NHWC scratch (static __device__ arrays: no runtime alloc)
__device__ float g_bufA[TOT];
__device__ float g_bufB[TOT];

__device__ __forceinline__ float4 ldcs4(const float* p) {
    return __ldcs((const float4*)p);
}

// One scan step: carry d0..d3 (pre-relu state, 4 consecutive channels per lane),
// conv along C via lane shuffles, zero-padded at C boundaries.
// d_new = relu(conv(d) + b) + x
__device__ __forceinline__ void scan_step(float& d0, float& d1, float& d2, float& d3,
                                          float x0, float x1, float x2, float x3,
                                          const float wk[9], float b, int lane)
{
    float v[12];
    v[4] = d0; v[5] = d1; v[6] = d2; v[7] = d3;
    v[0]  = __shfl_up_sync(FULLMASK, d0, 1);
    v[1]  = __shfl_up_sync(FULLMASK, d1, 1);
    v[2]  = __shfl_up_sync(FULLMASK, d2, 1);
    v[3]  = __shfl_up_sync(FULLMASK, d3, 1);
    v[8]  = __shfl_down_sync(FULLMASK, d0, 1);
    v[9]  = __shfl_down_sync(FULLMASK, d1, 1);
    v[10] = __shfl_down_sync(FULLMASK, d2, 1);
    v[11] = __shfl_down_sync(FULLMASK, d3, 1);
    if (lane == 0)  { v[0] = 0.f; v[1] = 0.f; v[2]  = 0.f; v[3]  = 0.f; }
    if (lane == 31) { v[8] = 0.f; v[9] = 0.f; v[10] = 0.f; v[11] = 0.f; }
    float a0 = b, a1 = b, a2 = b, a3 = b;
#pragma unroll
    for (int k = 0; k < 9; k++) {
        a0 = fmaf(wk[k], v[k + 0], a0);
        a1 = fmaf(wk[k], v[k + 1], a1);
        a2 = fmaf(wk[k], v[k + 2], a2);
        a3 = fmaf(wk[k], v[k + 3], a3);
    }
    d0 = fmaxf(a0, 0.f) + x0;
    d1 = fmaxf(a1, 0.f) + x1;
    d2 = fmaxf(a2, 0.f) + x2;
    d3 = fmaxf(a3, 0.f) + x3;
}

__device__ __forceinline__ float4 relu4(float a, float b, float c, float d) {
    return make_float4(fmaxf(a, 0.f), fmaxf(b, 0.f), fmaxf(c, 0.f), fmaxf(d, 0.f));
}

// NHWC->NHWC scan over one column with depth-8 register prefetch.
// inp/outp point at the FIRST scan element (+c0); stride signed (floats).
__device__ __forceinline__ void scan_col_pf(const float* __restrict__ inp,
                                            float* __restrict__ outp,
                                            int stride, const float wk[9], float b, int lane)
{
    float4 q[8];
    float4 v0 = ldcs4(inp);
    float d0 = v0.x, d1 = v0.y, d2 = v0.z, d3 = v0.w;
    *(float4*)outp = relu4(d0, d1, d2, d3);
#pragma unroll
    for (int i = 0; i < 8; i++) q[i] = ldcs4(inp + (1 + i) * stride);
    for (int t = 1; t < 160; t++) {
        float4 cx = q[(t - 1) & 7];
        if (t + 8 < 160) q[(t - 1) & 7] = ldcs4(inp + (t + 8) * stride);
        scan_step(d0, d1, d2, d3, cx.x, cx.y, cx.z, cx.w, wk, b, lane);
        *(float4*)(outp + t * stride) = relu4(d0, d1, d2, d3);
    }
}

// Pass 1 (down, scan over H ascending): reads x in NCHW via smem-staged
// cooperative transpose (1 coalesced-per-c LDG.128 per thread per step),
// writes NHWC g_bufA. Depth-4 prefetch pipeline on the staging loads.
__global__ void __launch_bounds__(128) k_pass1(const float* __restrict__ x,
                                               const float* __restrict__ wgt,
                                               const float* __restrict__ bia)
{
    __shared__ float sm[2][4][128];      // [phase][w-offset][c]
    const int tid = threadIdx.x, lane = tid & 31, warp = tid >> 5;
    const int col0 = blockIdx.x * 4;     // 4 consecutive w, same n (160 % 4 == 0)
    const int n = col0 / Ww, w0 = col0 % Ww;
    float wk[9];
#pragma unroll
    for (int k = 0; k < 9; k++) wk[k] = wgt[k];
    const float b = bia[0];
    const int c0 = lane * 4;

    // NCHW: each thread owns channel c=tid, loads float4 over w0..w0+3
    const float* xb = x + ((size_t)n * Cc + tid) * (Hh * Ww) + w0;   // + h*Ww
    // NHWC out for this warp's column (w0 + warp)
    float* ob = g_bufA + (size_t)n * HWC + (size_t)(w0 + warp) * Cc + c0;

    constexpr int D = 4;
    float4 q[D];
#pragma unroll
    for (int i = 0; i < D; i++) q[i] = ldcs4(xb + i * Ww);

    float d0 = 0.f, d1 = 0.f, d2 = 0.f, d3 = 0.f;
    for (int h = 0; h < Hh; h++) {
        float4 v = q[h & (D - 1)];
        sm[h & 1][0][tid] = v.x;
        sm[h & 1][1][tid] = v.y;
        sm[h & 1][2][tid] = v.z;
        sm[h & 1][3][tid] = v.w;
        if (h + D < Hh) q[h & (D - 1)] = ldcs4(xb + (h + D) * Ww);
        __syncthreads();
        float4 cx = *(const float4*)&sm[h & 1][warp][c0];
        if (h == 0) {
            d0 = cx.x; d1 = cx.y; d2 = cx.z; d3 = cx.w;
        } else {
            scan_step(d0, d1, d2, d3, cx.x, cx.y, cx.z, cx.w, wk, b, lane);
        }
        *(float4*)(ob + h * (Ww * Cc)) = relu4(d0, d1, d2, d3);
    }
}

// Pass 2 (up, scan over H descending): g_bufA -> g_bufB, NHWC.
__global__ void __launch_bounds__(128) k_pass2(const float* __restrict__ wgt,
                                               const float* __restrict__ bia)
{
    const int lane = threadIdx.x & 31, warp = threadIdx.x >> 5;
    const int col = blockIdx.x * 4 + warp;   // n*W + w
    const int n = col / Ww, w = col % Ww;
    float wk[9];
#pragma unroll
    for (int k = 0; k < 9; k++) wk[k] = wgt[k];
    const float b = bia[0];
    const int c0 = lane * 4;
    const int base = n * HWC + (Hh - 1) * (Ww * Cc) + w * Cc + c0;  // start at h = H-1
    scan_col_pf(g_bufA + base, g_bufB + base, -(Ww * Cc), wk, b, lane);
}

// Pass 3 (left, scan over W ascending): g_bufB -> g_bufA, NHWC.
__global__ void __launch_bounds__(128) k_pass3(const float* __restrict__ wgt,
                                               const float* __restrict__ bia)
{
    const int lane = threadIdx.x & 31, warp = threadIdx.x >> 5;
    const int col = blockIdx.x * 4 + warp;   // n*H + h
    const int n = col / Hh, h = col % Hh;
    float wk[9];
#pragma unroll
    for (int k = 0; k < 9; k++) wk[k] = wgt[k];
    const float b = bia[0];
    const int c0 = lane * 4;
    const int base = n * HWC + h * (Ww * Cc) + c0;                   // start at w = 0
    scan_col_pf(g_bufB + base, g_bufA + base, Cc, wk, b, lane);
}

// Pass 4 (right, scan over W descending): g_bufA (NHWC) -> d_out in NCHW with
// both spatial axes flipped (reference never un-flips). Output staged in smem
// per 16-step tile so NCHW stores are 64B-contiguous. Depth-8 read prefetch.
__global__ void __launch_bounds__(128) k_pass4(const float* __restrict__ wgt,
                                               const float* __restrict__ bia,
                                               float* __restrict__ out)
{
    __shared__ float stage[4][16][128];   // [warp(h)][tile-w][c] = 32 KB
    const int lane = threadIdx.x & 31, warp = threadIdx.x >> 5;
    const int col = blockIdx.x * 4 + warp;   // n*H + h
    const int n = col / Hh, h = col % Hh;
    const int col0 = blockIdx.x * 4;         // 4|160 so whole block shares n
    const int nb = col0 / Hh, hb = col0 % Hh;
    float wk[9];
#pragma unroll
    for (int k = 0; k < 9; k++) wk[k] = wgt[k];
    const float b = bia[0];
    const int c0 = lane * 4;

    const float* inp = g_bufA + n * HWC + h * (Ww * Cc) + c0;  // + w*Cc
    // s = 0 corresponds to w = W-1; s ascends as w descends.

    float4 v0 = ldcs4(inp + (Ww - 1) * Cc);
    float d0 = v0.x, d1 = v0.y, d2 = v0.z, d3 = v0.w;
    *(float4*)&stage[warp][0][c0] = relu4(d0, d1, d2, d3);

    float4 q[8];
#pragma unroll
    for (int i = 0; i < 8; i++) q[i] = ldcs4(inp + (Ww - 2 - i) * Cc);  // s = 1+i

    for (int s = 1; s < 160; s++) {
        float4 cx = q[(s - 1) & 7];
        if (s + 8 < 160) q[(s - 1) & 7] = ldcs4(inp + (Ww - 1 - (s + 8)) * Cc);
        scan_step(d0, d1, d2, d3, cx.x, cx.y, cx.z, cx.w, wk, b, lane);
        *(float4*)&stage[warp][s & 15][c0] = relu4(d0, d1, d2, d3);

        if ((s & 15) == 15) {                // flush 16-wide output tile
            __syncthreads();
            const int s0 = s - 15;
#pragma unroll
            for (int k = 0; k < 4; k++) {
                const int row = k * 128 + threadIdx.x;   // 512 rows: (h-in-block, c)
                const int j = row >> 7, c = row & 127;
                float* op = out + (((size_t)nb * Cc + c) * Hh + (Hh - 1 - (hb + j))) * Ww + s0;
#pragma unroll
                for (int t = 0; t < 4; t++) {
                    float4 val = make_float4(stage[j][4 * t + 0][c], stage[j][4 * t + 1][c],
                                             stage[j][4 * t + 2][c], stage[j][4 * t + 3][c]);
                    ((float4*)op)[t] = val;
                }
            }
            __syncthreads();
        }
    }
}

extern "C" void kernel_launch(void* const* d_in, const int* in_sizes, int n_in,
                              void* d_out, int out_size)
{
    (void)in_sizes; (void)n_in; (void)out_size;
    const float* x  = (const float*)d_in[0];
    const float* wd = (const float*)d_in[1];
    const float* bd = (const float*)d_in[2];
    const float* wu = (const float*)d_in[3];
    const float* bu = (const float*)d_in[4];
    const float* wl = (const float*)d_in[5];
    const float* bl = (const float*)d_in[6];
    const float* wr = (const float*)d_in[7];
    const float* br = (const float*)d_in[8];
    float* out = (float*)d_out;

    k_pass1<<<320, 128>>>(x, wd, bd);
    k_pass2<<<320, 128>>>(wu, bu);
    k_pass3<<<320, 128>>>(wl, bl);
    k_pass4<<<320, 128>>>(wr, br, out);
}

// round 4
// speedup vs baseline: 1.3030x; 1.3030x over previous
#include <cuda_runtime.h>

#define FULLMASK 0xffffffffu

constexpr int Nn = 8;
constexpr int Cc = 128;
constexpr int Hh = 160;
constexpr int Ww = 160;
constexpr int HWC = Hh * Ww * Cc;        // per-image NHWC stride
constexpr int TOT = Nn * HWC;            // 26,214,400

// Single in-place NHWC scratch buffer (105 MB — fits L2). Static __device__.
__device__ float g_buf[TOT];

__device__ __forceinline__ float4 ld4(const float* p)  { return *(const float4*)p; }
__device__ __forceinline__ float4 ldcs4(const float* p){ return __ldcs((const float4*)p); }

__device__ __forceinline__ float4 relu4(float a, float b, float c, float d) {
    return make_float4(fmaxf(a, 0.f), fmaxf(b, 0.f), fmaxf(c, 0.f), fmaxf(d, 0.f));
}

// One scan step: carry d0..d3 (pre-relu state, 4 consecutive channels/lane),
// 9-tap conv along C via lane shuffles, zero-padded at C boundaries.
// d_new = relu(conv(d) + b) + x.  Split accumulators shorten the FMA chain.
__device__ __forceinline__ void scan_step(float& d0, float& d1, float& d2, float& d3,
                                          float x0, float x1, float x2, float x3,
                                          const float wk[9], float b, int lane)
{
    float v[12];
    v[4] = d0; v[5] = d1; v[6] = d2; v[7] = d3;
    v[0]  = __shfl_up_sync(FULLMASK, d0, 1);
    v[1]  = __shfl_up_sync(FULLMASK, d1, 1);
    v[2]  = __shfl_up_sync(FULLMASK, d2, 1);
    v[3]  = __shfl_up_sync(FULLMASK, d3, 1);
    v[8]  = __shfl_down_sync(FULLMASK, d0, 1);
    v[9]  = __shfl_down_sync(FULLMASK, d1, 1);
    v[10] = __shfl_down_sync(FULLMASK, d2, 1);
    v[11] = __shfl_down_sync(FULLMASK, d3, 1);
    if (lane == 0)  { v[0] = 0.f; v[1] = 0.f; v[2]  = 0.f; v[3]  = 0.f; }
    if (lane == 31) { v[8] = 0.f; v[9] = 0.f; v[10] = 0.f; v[11] = 0.f; }
    float a0 = b, a1 = b, a2 = b, a3 = b;
    float e0 = 0.f, e1 = 0.f, e2 = 0.f, e3 = 0.f;
#pragma unroll
    for (int k = 0; k < 5; k++) {
        a0 = fmaf(wk[k], v[k + 0], a0);
        a1 = fmaf(wk[k], v[k + 1], a1);
        a2 = fmaf(wk[k], v[k + 2], a2);
        a3 = fmaf(wk[k], v[k + 3], a3);
    }
#pragma unroll
    for (int k = 5; k < 9; k++) {
        e0 = fmaf(wk[k], v[k + 0], e0);
        e1 = fmaf(wk[k], v[k + 1], e1);
        e2 = fmaf(wk[k], v[k + 2], e2);
        e3 = fmaf(wk[k], v[k + 3], e3);
    }
    d0 = fmaxf(a0 + e0, 0.f) + x0;
    d1 = fmaxf(a1 + e1, 0.f) + x1;
    d2 = fmaxf(a2 + e2, 0.f) + x2;
    d3 = fmaxf(a3 + e3, 0.f) + x3;
}

// In-place NHWC scan over one column. Depth-8 prefetch with STATIC queue
// indices (tiled + fully-unrolled inner loop). p points at scan element 0 (+c0);
// stride signed (floats). Forward-only writes => in-place is safe.
__device__ __forceinline__ void scan_col_ip(float* __restrict__ p, int stride,
                                            const float wk[9], float b, int lane)
{
    float4 q[8];
    float4 v0 = ld4(p);
    float d0 = v0.x, d1 = v0.y, d2 = v0.z, d3 = v0.w;
    *(float4*)p = relu4(d0, d1, d2, d3);
#pragma unroll
    for (int i = 0; i < 8; i++) q[i] = ld4(p + (1 + i) * stride);
    for (int tb = 1; tb < 160; tb += 8) {
#pragma unroll
        for (int i = 0; i < 8; i++) {
            const int t = tb + i;
            if (t < 160) {
                float4 cx = q[i];
                if (t + 8 < 160) q[i] = ld4(p + (t + 8) * stride);
                scan_step(d0, d1, d2, d3, cx.x, cx.y, cx.z, cx.w, wk, b, lane);
                *(float4*)(p + t * stride) = relu4(d0, d1, d2, d3);
            }
        }
    }
}

// Pass 1 (down, scan over H ascending): reads x NCHW via smem-staged
// cooperative transpose (one coalesced LDG.128/thread/step, depth-8 pipeline),
// writes NHWC g_buf.
__global__ void __launch_bounds__(128) k_pass1(const float* __restrict__ x,
                                               const float* __restrict__ wgt,
                                               const float* __restrict__ bia)
{
    __shared__ float sm[2][4][128];      // [phase][w-offset][c]
    const int tid = threadIdx.x, lane = tid & 31, warp = tid >> 5;
    const int col0 = blockIdx.x * 4;     // 4 consecutive w, same n (160 % 4 == 0)
    const int n = col0 / Ww, w0 = col0 % Ww;
    float wk[9];
#pragma unroll
    for (int k = 0; k < 9; k++) wk[k] = wgt[k];
    const float b = bia[0];
    const int c0 = lane * 4;

    const float* xb = x + ((size_t)n * Cc + tid) * (Hh * Ww) + w0;   // + h*Ww
    float* ob = g_buf + (size_t)n * HWC + (size_t)(w0 + warp) * Cc + c0;

    float4 q[8];
#pragma unroll
    for (int i = 0; i < 8; i++) q[i] = ldcs4(xb + i * Ww);

    float d0 = 0.f, d1 = 0.f, d2 = 0.f, d3 = 0.f;
    for (int hb = 0; hb < 160; hb += 8) {
#pragma unroll
        for (int i = 0; i < 8; i++) {
            const int h = hb + i;
            float4 v = q[i];
            sm[h & 1][0][tid] = v.x;
            sm[h & 1][1][tid] = v.y;
            sm[h & 1][2][tid] = v.z;
            sm[h & 1][3][tid] = v.w;
            if (h + 8 < Hh) q[i] = ldcs4(xb + (h + 8) * Ww);
            __syncthreads();
            float4 cx = *(const float4*)&sm[h & 1][warp][c0];
            if (h == 0) {
                d0 = cx.x; d1 = cx.y; d2 = cx.z; d3 = cx.w;
            } else {
                scan_step(d0, d1, d2, d3, cx.x, cx.y, cx.z, cx.w, wk, b, lane);
            }
            *(float4*)(ob + h * (Ww * Cc)) = relu4(d0, d1, d2, d3);
        }
    }
}

// Pass 2 (up, H descending) — in place.
__global__ void __launch_bounds__(128) k_pass2(const float* __restrict__ wgt,
                                               const float* __restrict__ bia)
{
    const int lane = threadIdx.x & 31, warp = threadIdx.x >> 5;
    const int col = blockIdx.x * 4 + warp;   // n*W + w
    const int n = col / Ww, w = col % Ww;
    float wk[9];
#pragma unroll
    for (int k = 0; k < 9; k++) wk[k] = wgt[k];
    const float b = bia[0];
    const int c0 = lane * 4;
    const int base = n * HWC + (Hh - 1) * (Ww * Cc) + w * Cc + c0;  // h = H-1
    scan_col_ip(g_buf + base, -(Ww * Cc), wk, b, lane);
}

// Pass 3 (left, W ascending) — in place.
__global__ void __launch_bounds__(128) k_pass3(const float* __restrict__ wgt,
                                               const float* __restrict__ bia)
{
    const int lane = threadIdx.x & 31, warp = threadIdx.x >> 5;
    const int col = blockIdx.x * 4 + warp;   // n*H + h
    const int n = col / Hh, h = col % Hh;
    float wk[9];
#pragma unroll
    for (int k = 0; k < 9; k++) wk[k] = wgt[k];
    const float b = bia[0];
    const int c0 = lane * 4;
    const int base = n * HWC + h * (Ww * Cc) + c0;                   // w = 0
    scan_col_ip(g_buf + base, Cc, wk, b, lane);
}

// Pass 4 (right, W descending): g_buf (NHWC) -> d_out NCHW with both spatial
// axes flipped (reference never un-flips). 16-step smem staging for coalesced
// NCHW stores; depth-8 static prefetch on reads.
__global__ void __launch_bounds__(128) k_pass4(const float* __restrict__ wgt,
                                               const float* __restrict__ bia,
                                               float* __restrict__ out)
{
    __shared__ float stage[4][16][128];   // [warp(h)][tile-w][c] = 32 KB
    const int lane = threadIdx.x & 31, warp = threadIdx.x >> 5;
    const int col = blockIdx.x * 4 + warp;   // n*H + h
    const int n = col / Hh, h = col % Hh;
    const int col0 = blockIdx.x * 4;         // 4|160 so whole block shares n
    const int nb = col0 / Hh, hb = col0 % Hh;
    float wk[9];
#pragma unroll
    for (int k = 0; k < 9; k++) wk[k] = wgt[k];
    const float b = bia[0];
    const int c0 = lane * 4;

    const float* inp = g_buf + n * HWC + h * (Ww * Cc) + c0;  // + w*Cc
    // s = 0 <-> w = W-1; s ascends as w descends.

    float4 v0 = ld4(inp + (Ww - 1) * Cc);
    float d0 = v0.x, d1 = v0.y, d2 = v0.z, d3 = v0.w;
    *(float4*)&stage[warp][0][c0] = relu4(d0, d1, d2, d3);

    float4 q[8];
#pragma unroll
    for (int i = 0; i < 8; i++) q[i] = ld4(inp + (Ww - 2 - i) * Cc);  // s = 1+i

    for (int sb = 1; sb < 160; sb += 8) {
#pragma unroll
        for (int i = 0; i < 8; i++) {
            const int s = sb + i;
            if (s < 160) {
                float4 cx = q[i];
                if (s + 8 < 160) q[i] = ld4(inp + (Ww - 1 - (s + 8)) * Cc);
                scan_step(d0, d1, d2, d3, cx.x, cx.y, cx.z, cx.w, wk, b, lane);
                *(float4*)&stage[warp][s & 15][c0] = relu4(d0, d1, d2, d3);

                if ((s & 15) == 15) {                // flush 16-wide output tile
                    __syncthreads();
                    const int s0 = s - 15;
#pragma unroll
                    for (int k = 0; k < 4; k++) {
                        const int row = k * 128 + threadIdx.x;  // (h-in-block, c)
                        const int j = row >> 7, c = row & 127;
                        float* op = out + (((size_t)nb * Cc + c) * Hh +
                                           (Hh - 1 - (hb + j))) * Ww + s0;
#pragma unroll
                        for (int t = 0; t < 4; t++) {
                            float4 val = make_float4(stage[j][4*t+0][c], stage[j][4*t+1][c],
                                                     stage[j][4*t+2][c], stage[j][4*t+3][c]);
                            __stcs(((float4*)op) + t, val);
                        }
                    }
                    __syncthreads();
                }
            }
        }
    }
}

extern "C" void kernel_launch(void* const* d_in, const int* in_sizes, int n_in,
                              void* d_out, int out_size)
{
    (void)in_sizes; (void)n_in; (void)out_size;
    const float* x  = (const float*)d_in[0];
    const float* wd = (const float*)d_in[1];
    const float* bd = (const float*)d_in[2];
    const float* wu = (const float*)d_in[3];
    const float* bu = (const float*)d_in[4];
    const float* wl = (const float*)d_in[5];
    const float* bl = (const float*)d_in[6];
    const float* wr = (const float*)d_in[7];
    const float* br = (const float*)d_in[8];
    float* out = (float*)d_out;

    k_pass1<<<320, 128>>>(x, wd, bd);
    k_pass2<<<320, 128>>>(wu, bu);
    k_pass3<<<320, 128>>>(wl, bl);
    k_pass4<<<320, 128>>>(wr, br, out);
}

// round 5
// speedup vs baseline: 2.5052x; 1.9227x over previous
#include <cuda_runtime.h>
#include <cuda_pipeline.h>

#define FULLMASK 0xffffffffu

constexpr int Nn = 8;
constexpr int Cc = 128;
constexpr int Hh = 160;
constexpr int Ww = 160;
constexpr int HWC = Hh * Ww * Cc;        // per-image NHWC stride
constexpr int TOT = Nn * HWC;            // 26,214,400

// Single in-place NHWC scratch buffer (105 MB — mostly L2-resident).
__device__ float g_buf[TOT];

__device__ __forceinline__ float4 ld4(const float* p)  { return *(const float4*)p; }

__device__ __forceinline__ float4 relu4(float a, float b, float c, float d) {
    return make_float4(fmaxf(a, 0.f), fmaxf(b, 0.f), fmaxf(c, 0.f), fmaxf(d, 0.f));
}

// One scan step: carry d0..d3 (pre-relu state, 4 consecutive channels/lane),
// 9-tap conv along C via lane shuffles, zero-padded at C boundaries.
// d_new = relu(conv(d) + b) + x. Split accumulators shorten the FMA chain.
__device__ __forceinline__ void scan_step(float& d0, float& d1, float& d2, float& d3,
                                          float x0, float x1, float x2, float x3,
                                          const float wk[9], float b, int lane)
{
    float v[12];
    v[4] = d0; v[5] = d1; v[6] = d2; v[7] = d3;
    v[0]  = __shfl_up_sync(FULLMASK, d0, 1);
    v[1]  = __shfl_up_sync(FULLMASK, d1, 1);
    v[2]  = __shfl_up_sync(FULLMASK, d2, 1);
    v[3]  = __shfl_up_sync(FULLMASK, d3, 1);
    v[8]  = __shfl_down_sync(FULLMASK, d0, 1);
    v[9]  = __shfl_down_sync(FULLMASK, d1, 1);
    v[10] = __shfl_down_sync(FULLMASK, d2, 1);
    v[11] = __shfl_down_sync(FULLMASK, d3, 1);
    if (lane == 0)  { v[0] = 0.f; v[1] = 0.f; v[2]  = 0.f; v[3]  = 0.f; }
    if (lane == 31) { v[8] = 0.f; v[9] = 0.f; v[10] = 0.f; v[11] = 0.f; }
    float a0 = b, a1 = b, a2 = b, a3 = b;
    float e0 = 0.f, e1 = 0.f, e2 = 0.f, e3 = 0.f;
#pragma unroll
    for (int k = 0; k < 5; k++) {
        a0 = fmaf(wk[k], v[k + 0], a0);
        a1 = fmaf(wk[k], v[k + 1], a1);
        a2 = fmaf(wk[k], v[k + 2], a2);
        a3 = fmaf(wk[k], v[k + 3], a3);
    }
#pragma unroll
    for (int k = 5; k < 9; k++) {
        e0 = fmaf(wk[k], v[k + 0], e0);
        e1 = fmaf(wk[k], v[k + 1], e1);
        e2 = fmaf(wk[k], v[k + 2], e2);
        e3 = fmaf(wk[k], v[k + 3], e3);
    }
    d0 = fmaxf(a0 + e0, 0.f) + x0;
    d1 = fmaxf(a1 + e1, 0.f) + x1;
    d2 = fmaxf(a2 + e2, 0.f) + x2;
    d3 = fmaxf(a3 + e3, 0.f) + x3;
}

// In-place NHWC column scan with an explicit cp.async ring (depth 8).
// ring: per-warp smem, 8 slots x 512 B. p -> element 0 (+c0); stride signed.
// In-place safety: element t's async read is waited before the STG to t, and
// outstanding copies only target elements > t.
__device__ __forceinline__ void scan_col_ring(float* __restrict__ p, int stride,
                                              float* __restrict__ ring,
                                              const float wk[9], float b, int lane)
{
    float4 v0 = ld4(p);
    float d0 = v0.x, d1 = v0.y, d2 = v0.z, d3 = v0.w;
    *(float4*)p = relu4(d0, d1, d2, d3);

    float* my = ring + lane * 4;   // slot s at ring + s*128 (+lane*4)
#pragma unroll
    for (int i = 0; i < 8; i++) {
        __pipeline_memcpy_async(my + i * 128, p + (1 + i) * stride, 16);
        __pipeline_commit();
    }
    for (int t = 1; t < 160; t++) {
        __pipeline_wait_prior(7);                 // element t is complete
        float* sl = my + ((t - 1) & 7) * 128;
        float4 cx = *(float4*)sl;
        if (t + 8 < 160)
            __pipeline_memcpy_async(sl, p + (t + 8) * stride, 16);
        __pipeline_commit();                      // uniform group count
        scan_step(d0, d1, d2, d3, cx.x, cx.y, cx.z, cx.w, wk, b, lane);
        *(float4*)(p + t * stride) = relu4(d0, d1, d2, d3);
    }
}

// Pass 1 (down, H ascending): x NCHW -> g_buf NHWC.
// cp.async ring (13 slots, depth 12) does gmem->smem staging; the transpose
// happens on the smem read side. Slot rows are 16B chunks with a 16B gap every
// 8 rows so cp.async stays 16B-aligned while transposed reads are 4-way max.
__global__ void __launch_bounds__(128) k_pass1(const float* __restrict__ x,
                                               const float* __restrict__ wgt,
                                               const float* __restrict__ bia)
{
    constexpr int SLOTS = 13, DEPTH = 12, SLOTW = 128 * 4 + 16 * 4;  // 576 words
    __shared__ float r1[SLOTS * SLOTW];          // ~30 KB
    const int tid = threadIdx.x, lane = tid & 31, warp = tid >> 5;
    const int col0 = blockIdx.x * 4;             // 4 consecutive w, same n
    const int n = col0 / Ww, w0 = col0 % Ww;
    float wk[9];
#pragma unroll
    for (int k = 0; k < 9; k++) wk[k] = wgt[k];
    const float b = bia[0];

    const float* xb = x + ((size_t)n * Cc + tid) * (Hh * Ww) + w0;   // + h*Ww
    float* ob = g_buf + (size_t)n * HWC + (size_t)(w0 + warp) * Cc + lane * 4;

    const int dstw = tid * 4 + (tid >> 3) * 4;   // this thread's chunk offset
#pragma unroll
    for (int i = 0; i < DEPTH; i++) {
        __pipeline_memcpy_async(r1 + i * SLOTW + dstw, xb + i * Ww, 16);
        __pipeline_commit();
    }

    // transposed read offsets for channels 4*lane .. 4*lane+3, column `warp`
    const int cA = 4 * lane;
    int rx0 = (cA + 0) * 4 + ((cA + 0) >> 3) * 4 + warp;
    int rx1 = (cA + 1) * 4 + ((cA + 1) >> 3) * 4 + warp;
    int rx2 = (cA + 2) * 4 + ((cA + 2) >> 3) * 4 + warp;
    int rx3 = (cA + 3) * 4 + ((cA + 3) >> 3) * 4 + warp;

    float d0 = 0.f, d1 = 0.f, d2 = 0.f, d3 = 0.f;
    int sl_r = 0, sl_w = DEPTH;
    for (int h = 0; h < Hh; h++) {
        __pipeline_wait_prior(DEPTH - 1);        // element h complete (this thread)
        __syncthreads();                         // all threads' copies + ordering
        const float* base = r1 + sl_r * SLOTW;
        float cx0 = base[rx0], cx1 = base[rx1], cx2 = base[rx2], cx3 = base[rx3];
        if (h + DEPTH < Hh)
            __pipeline_memcpy_async(r1 + sl_w * SLOTW + dstw, xb + (h + DEPTH) * Ww, 16);
        __pipeline_commit();
        if (h == 0) { d0 = cx0; d1 = cx1; d2 = cx2; d3 = cx3; }
        else scan_step(d0, d1, d2, d3, cx0, cx1, cx2, cx3, wk, b, lane);
        *(float4*)(ob + h * (Ww * Cc)) = relu4(d0, d1, d2, d3);
        sl_r = (sl_r + 1 == SLOTS) ? 0 : sl_r + 1;
        sl_w = (sl_w + 1 == SLOTS) ? 0 : sl_w + 1;
    }
}

// Pass 2 (up, H descending) — in place.
__global__ void __launch_bounds__(128) k_pass2(const float* __restrict__ wgt,
                                               const float* __restrict__ bia)
{
    __shared__ float ring[4][8 * 128];           // 16 KB
    const int lane = threadIdx.x & 31, warp = threadIdx.x >> 5;
    const int col = blockIdx.x * 4 + warp;       // n*W + w
    const int n = col / Ww, w = col % Ww;
    float wk[9];
#pragma unroll
    for (int k = 0; k < 9; k++) wk[k] = wgt[k];
    const float b = bia[0];
    const int base = n * HWC + (Hh - 1) * (Ww * Cc) + w * Cc + lane * 4;  // h = H-1
    scan_col_ring(g_buf + base, -(Ww * Cc), ring[warp], wk, b, lane);
}

// Pass 3 (left, W ascending) — in place.
__global__ void __launch_bounds__(128) k_pass3(const float* __restrict__ wgt,
                                               const float* __restrict__ bia)
{
    __shared__ float ring[4][8 * 128];
    const int lane = threadIdx.x & 31, warp = threadIdx.x >> 5;
    const int col = blockIdx.x * 4 + warp;       // n*H + h
    const int n = col / Hh, h = col % Hh;
    float wk[9];
#pragma unroll
    for (int k = 0; k < 9; k++) wk[k] = wgt[k];
    const float b = bia[0];
    const int base = n * HWC + h * (Ww * Cc) + lane * 4;                  // w = 0
    scan_col_ring(g_buf + base, Cc, ring[warp], wk, b, lane);
}

// Pass 4 (right, W descending): g_buf NHWC -> d_out NCHW with both spatial
// axes flipped (reference never un-flips). cp.async ring for reads; 16-step
// warp-private smem staging; remapped flush so each STG.128 covers 8 full
// 64B gmem lines (c-major across lane quads).
constexpr int PC = 132;                          // stage row pitch (2-way LDS max)

__global__ void __launch_bounds__(128) k_pass4(const float* __restrict__ wgt,
                                               const float* __restrict__ bia,
                                               float* __restrict__ out)
{
    __shared__ float ring[4][8 * 128];           // 16 KB
    __shared__ float stage[4][16][PC];           // ~33.8 KB
    const int lane = threadIdx.x & 31, warp = threadIdx.x >> 5;
    const int col = blockIdx.x * 4 + warp;       // n*H + h
    const int n = col / Hh, h = col % Hh;
    float wk[9];
#pragma unroll
    for (int k = 0; k < 9; k++) wk[k] = wgt[k];
    const float b = bia[0];
    const int c0 = lane * 4;

    const float* inp = g_buf + n * HWC + h * (Ww * Cc) + c0;  // + w*Cc
    // s = 0 <-> w = W-1; s ascends as w descends.

    float4 v0 = ld4(inp + (Ww - 1) * Cc);
    float d0 = v0.x, d1 = v0.y, d2 = v0.z, d3 = v0.w;
    *(float4*)&stage[warp][0][c0] = relu4(d0, d1, d2, d3);

    float* my = ring[warp] + lane * 4;
#pragma unroll
    for (int i = 0; i < 8; i++) {                // element s = 1+i
        __pipeline_memcpy_async(my + i * 128, inp + (Ww - 2 - i) * Cc, 16);
        __pipeline_commit();
    }

    // flush lane mapping: quad q = lane>>2 -> channel offset, tq = lane&3 -> w chunk
    const int tq = lane & 3, cq = lane >> 2;
    const int hrow = Hh - 1 - h;                 // flipped output h

    for (int s = 1; s < 160; s++) {
        __pipeline_wait_prior(7);
        float* sl = my + ((s - 1) & 7) * 128;
        float4 cx = *(float4*)sl;
        if (s + 8 < 160)
            __pipeline_memcpy_async(sl, inp + (Ww - 1 - (s + 8)) * Cc, 16);
        __pipeline_commit();
        scan_step(d0, d1, d2, d3, cx.x, cx.y, cx.z, cx.w, wk, b, lane);
        *(float4*)&stage[warp][s & 15][c0] = relu4(d0, d1, d2, d3);

        if ((s & 15) == 15) {                    // warp-private flush of 16 w's
            __syncwarp();
            const int s0 = s - 15;
#pragma unroll
            for (int cb = 0; cb < 16; cb++) {
                const int c = cb * 8 + cq;
                float4 val = make_float4(stage[warp][4 * tq + 0][c],
                                         stage[warp][4 * tq + 1][c],
                                         stage[warp][4 * tq + 2][c],
                                         stage[warp][4 * tq + 3][c]);
                float* op = out + (((size_t)n * Cc + c) * Hh + hrow) * Ww + s0 + 4 * tq;
                __stcs((float4*)op, val);
            }
            __syncwarp();
        }
    }
}

extern "C" void kernel_launch(void* const* d_in, const int* in_sizes, int n_in,
                              void* d_out, int out_size)
{
    (void)in_sizes; (void)n_in; (void)out_size;
    const float* x  = (const float*)d_in[0];
    const float* wd = (const float*)d_in[1];
    const float* bd = (const float*)d_in[2];
    const float* wu = (const float*)d_in[3];
    const float* bu = (const float*)d_in[4];
    const float* wl = (const float*)d_in[5];
    const float* bl = (const float*)d_in[6];
    const float* wr = (const float*)d_in[7];
    const float* br = (const float*)d_in[8];
    float* out = (float*)d_out;

    k_pass1<<<320, 128>>>(x, wd, bd);
    k_pass2<<<320, 128>>>(wu, bu);
    k_pass3<<<320, 128>>>(wl, bl);
    k_pass4<<<320, 128>>>(wr, br, out);
}

// round 6
// speedup vs baseline: 2.5481x; 1.0171x over previous
#include <cuda_runtime.h>
#include <cuda_pipeline.h>

#define FULLMASK 0xffffffffu

constexpr int Nn = 8;
constexpr int Cc = 128;
constexpr int Hh = 160;
constexpr int Ww = 160;
constexpr int HWC = Hh * Ww * Cc;        // per-image NHWC stride
constexpr int TOT = Nn * HWC;

// Single in-place NHWC scratch buffer.
__device__ float g_buf[TOT];

__device__ __forceinline__ float4 ld4(const float* p)  { return *(const float4*)p; }

__device__ __forceinline__ float4 relu4(float a, float b, float c, float d) {
    return make_float4(fmaxf(a, 0.f), fmaxf(b, 0.f), fmaxf(c, 0.f), fmaxf(d, 0.f));
}

// One scan step: carry d0..d3 (pre-relu state, 4 consecutive channels/lane),
// 9-tap conv along C via lane shuffles, zero-padded at C boundaries.
// d_new = relu(conv(d) + b) + x. Split accumulators shorten the FMA chain.
__device__ __forceinline__ void scan_step(float& d0, float& d1, float& d2, float& d3,
                                          float x0, float x1, float x2, float x3,
                                          const float wk[9], float b, int lane)
{
    float v[12];
    v[4] = d0; v[5] = d1; v[6] = d2; v[7] = d3;
    v[0]  = __shfl_up_sync(FULLMASK, d0, 1);
    v[1]  = __shfl_up_sync(FULLMASK, d1, 1);
    v[2]  = __shfl_up_sync(FULLMASK, d2, 1);
    v[3]  = __shfl_up_sync(FULLMASK, d3, 1);
    v[8]  = __shfl_down_sync(FULLMASK, d0, 1);
    v[9]  = __shfl_down_sync(FULLMASK, d1, 1);
    v[10] = __shfl_down_sync(FULLMASK, d2, 1);
    v[11] = __shfl_down_sync(FULLMASK, d3, 1);
    if (lane == 0)  { v[0] = 0.f; v[1] = 0.f; v[2]  = 0.f; v[3]  = 0.f; }
    if (lane == 31) { v[8] = 0.f; v[9] = 0.f; v[10] = 0.f; v[11] = 0.f; }
    float a0 = b, a1 = b, a2 = b, a3 = b;
    float e0 = 0.f, e1 = 0.f, e2 = 0.f, e3 = 0.f;
#pragma unroll
    for (int k = 0; k < 5; k++) {
        a0 = fmaf(wk[k], v[k + 0], a0);
        a1 = fmaf(wk[k], v[k + 1], a1);
        a2 = fmaf(wk[k], v[k + 2], a2);
        a3 = fmaf(wk[k], v[k + 3], a3);
    }
#pragma unroll
    for (int k = 5; k < 9; k++) {
        e0 = fmaf(wk[k], v[k + 0], e0);
        e1 = fmaf(wk[k], v[k + 1], e1);
        e2 = fmaf(wk[k], v[k + 2], e2);
        e3 = fmaf(wk[k], v[k + 3], e3);
    }
    d0 = fmaxf(a0 + e0, 0.f) + x0;
    d1 = fmaxf(a1 + e1, 0.f) + x1;
    d2 = fmaxf(a2 + e2, 0.f) + x2;
    d3 = fmaxf(a3 + e3, 0.f) + x3;
}

// In-place NHWC column scan, cp.async ring depth 16, pair-unrolled.
// ring: per-warp smem, 16 slots x 512 B. p -> element 0 (+c0); stride signed.
__device__ __forceinline__ void scan_col_ring16(float* __restrict__ p, int stride,
                                                float* __restrict__ ring,
                                                const float wk[9], float b, int lane)
{
    float4 v0 = ld4(p);
    float d0 = v0.x, d1 = v0.y, d2 = v0.z, d3 = v0.w;
    *(float4*)p = relu4(d0, d1, d2, d3);

    float* my = ring + lane * 4;   // slot s at my + s*128
#pragma unroll
    for (int i = 0; i < 16; i++) {
        __pipeline_memcpy_async(my + i * 128, p + (1 + i) * stride, 16);
        __pipeline_commit();
    }
    for (int t = 1; t + 1 < 160; t += 2) {
        __pipeline_wait_prior(14);               // elements t, t+1 complete
        float* sl0 = my + ((t - 1) & 15) * 128;
        float* sl1 = my + (t & 15) * 128;
        float4 cx0 = *(float4*)sl0;
        float4 cx1 = *(float4*)sl1;
        if (t + 16 < 160) __pipeline_memcpy_async(sl0, p + (t + 16) * stride, 16);
        __pipeline_commit();
        if (t + 17 < 160) __pipeline_memcpy_async(sl1, p + (t + 17) * stride, 16);
        __pipeline_commit();
        scan_step(d0, d1, d2, d3, cx0.x, cx0.y, cx0.z, cx0.w, wk, b, lane);
        *(float4*)(p + t * stride) = relu4(d0, d1, d2, d3);
        scan_step(d0, d1, d2, d3, cx1.x, cx1.y, cx1.z, cx1.w, wk, b, lane);
        *(float4*)(p + (t + 1) * stride) = relu4(d0, d1, d2, d3);
    }
    // t = 159
    __pipeline_wait_prior(0);
    float4 cx = *(float4*)(my + ((159 - 1) & 15) * 128);
    scan_step(d0, d1, d2, d3, cx.x, cx.y, cx.z, cx.w, wk, b, lane);
    *(float4*)(p + 159 * stride) = relu4(d0, d1, d2, d3);
}

// Pass 1 (down, H ascending): x NCHW -> g_buf NHWC. cp.async staging ring
// (18 slots, depth 16), transpose on the smem read side, ONE __syncthreads
// per 2 elements. Slot rows: 16B chunks, 16B gap per 8 rows (alignment + low
// conflict on transposed reads).
__global__ void __launch_bounds__(128) k_pass1(const float* __restrict__ x,
                                               const float* __restrict__ wgt,
                                               const float* __restrict__ bia)
{
    constexpr int SLOTS = 18, DEPTH = 16, SLOTW = 128 * 4 + 16 * 4;  // 576 words
    __shared__ float r1[SLOTS * SLOTW];          // ~41.5 KB
    const int tid = threadIdx.x, lane = tid & 31, warp = tid >> 5;
    const int col0 = blockIdx.x * 4;             // 4 consecutive w, same n
    const int n = col0 / Ww, w0 = col0 % Ww;
    float wk[9];
#pragma unroll
    for (int k = 0; k < 9; k++) wk[k] = wgt[k];
    const float b = bia[0];

    const float* xb = x + ((size_t)n * Cc + tid) * (Hh * Ww) + w0;   // + h*Ww
    float* ob = g_buf + (size_t)n * HWC + (size_t)(w0 + warp) * Cc + lane * 4;

    const int dstw = tid * 4 + (tid >> 3) * 4;   // this thread's chunk offset
#pragma unroll
    for (int i = 0; i < DEPTH; i++) {
        __pipeline_memcpy_async(r1 + i * SLOTW + dstw, xb + i * Ww, 16);
        __pipeline_commit();
    }

    // transposed read offsets: channels 4*lane..+3 of column `warp`
    const int cA = 4 * lane;
    const int rx0 = (cA + 0) * 4 + ((cA + 0) >> 3) * 4 + warp;
    const int rx1 = (cA + 1) * 4 + ((cA + 1) >> 3) * 4 + warp;
    const int rx2 = (cA + 2) * 4 + ((cA + 2) >> 3) * 4 + warp;
    const int rx3 = (cA + 3) * 4 + ((cA + 3) >> 3) * 4 + warp;

    float d0 = 0.f, d1 = 0.f, d2 = 0.f, d3 = 0.f;
    int sl_r = 0, sl_w = DEPTH;
    for (int h = 0; h < 160; h += 2) {
        __pipeline_wait_prior(DEPTH - 2);        // this thread's h, h+1 landed
        __syncthreads();                         // all threads' copies visible
        int sr1 = sl_r + 1; if (sr1 == SLOTS) sr1 = 0;
        const float* b0 = r1 + sl_r * SLOTW;
        const float* b1 = r1 + sr1 * SLOTW;
        float c00 = b0[rx0], c01 = b0[rx1], c02 = b0[rx2], c03 = b0[rx3];
        float c10 = b1[rx0], c11 = b1[rx1], c12 = b1[rx2], c13 = b1[rx3];
        int sw1 = sl_w + 1; if (sw1 == SLOTS) sw1 = 0;
        if (h + DEPTH < Hh)
            __pipeline_memcpy_async(r1 + sl_w * SLOTW + dstw, xb + (h + DEPTH) * Ww, 16);
        __pipeline_commit();
        if (h + DEPTH + 1 < Hh)
            __pipeline_memcpy_async(r1 + sw1 * SLOTW + dstw, xb + (h + DEPTH + 1) * Ww, 16);
        __pipeline_commit();

        if (h == 0) { d0 = c00; d1 = c01; d2 = c02; d3 = c03; }
        else scan_step(d0, d1, d2, d3, c00, c01, c02, c03, wk, b, lane);
        *(float4*)(ob + h * (Ww * Cc)) = relu4(d0, d1, d2, d3);
        scan_step(d0, d1, d2, d3, c10, c11, c12, c13, wk, b, lane);
        *(float4*)(ob + (h + 1) * (Ww * Cc)) = relu4(d0, d1, d2, d3);

        sl_r += 2; if (sl_r >= SLOTS) sl_r -= SLOTS;
        sl_w += 2; if (sl_w >= SLOTS) sl_w -= SLOTS;
    }
}

// Pass 2 (up, H descending) — in place.
__global__ void __launch_bounds__(128) k_pass2(const float* __restrict__ wgt,
                                               const float* __restrict__ bia)
{
    __shared__ float ring[4][16 * 128];          // 32 KB
    const int lane = threadIdx.x & 31, warp = threadIdx.x >> 5;
    const int col = blockIdx.x * 4 + warp;       // n*W + w
    const int n = col / Ww, w = col % Ww;
    float wk[9];
#pragma unroll
    for (int k = 0; k < 9; k++) wk[k] = wgt[k];
    const float b = bia[0];
    const int base = n * HWC + (Hh - 1) * (Ww * Cc) + w * Cc + lane * 4;  // h = H-1
    scan_col_ring16(g_buf + base, -(Ww * Cc), ring[warp], wk, b, lane);
}

// Pass 3 (left, W ascending) — in place.
__global__ void __launch_bounds__(128) k_pass3(const float* __restrict__ wgt,
                                               const float* __restrict__ bia)
{
    __shared__ float ring[4][16 * 128];
    const int lane = threadIdx.x & 31, warp = threadIdx.x >> 5;
    const int col = blockIdx.x * 4 + warp;       // n*H + h
    const int n = col / Hh, h = col % Hh;
    float wk[9];
#pragma unroll
    for (int k = 0; k < 9; k++) wk[k] = wgt[k];
    const float b = bia[0];
    const int base = n * HWC + h * (Ww * Cc) + lane * 4;                  // w = 0
    scan_col_ring16(g_buf + base, Cc, ring[warp], wk, b, lane);
}

// Pass 4 (right, W descending): g_buf NHWC -> d_out NCHW, both spatial axes
// flipped (reference never un-flips). Depth-16 ring; warp-private 16-step
// stage with XOR swizzle (conflict-free read AND write); flush writes 8 full
// 64B lines per STG-round via (tq = w-chunk, cq = c-offset) lane mapping.
__device__ __forceinline__ void p4_stage_write(float* stg, int row, int c0,
                                               float4 val)
{
    const int pc = c0 ^ (8 * ((row >> 2) & 3));
    *(float4*)(stg + row * 128 + pc) = val;
}

__global__ void __launch_bounds__(128) k_pass4(const float* __restrict__ wgt,
                                               const float* __restrict__ bia,
                                               float* __restrict__ out)
{
    __shared__ float ring[4][16 * 128];          // 32 KB
    __shared__ float stage[4][16 * 128];         // 32 KB (swizzled)
    const int lane = threadIdx.x & 31, warp = threadIdx.x >> 5;
    const int col = blockIdx.x * 4 + warp;       // n*H + h
    const int n = col / Hh, h = col % Hh;
    float wk[9];
#pragma unroll
    for (int k = 0; k < 9; k++) wk[k] = wgt[k];
    const float b = bia[0];
    const int c0 = lane * 4;

    const float* inp = g_buf + n * HWC + h * (Ww * Cc) + c0;  // + w*Cc
    float* stg = stage[warp];
    const int tq = lane & 3, cq = lane >> 2;
    const int hrow = Hh - 1 - h;                 // flipped output h
    // out row base for flush: out[(n*Cc + c)*Hh*Ww + hrow*Ww + ...]
    float* const obase = out + ((size_t)n * Cc * Hh + hrow) * Ww;

    // s = 0 <-> w = W-1
    float4 v0 = ld4(inp + (Ww - 1) * Cc);
    float d0 = v0.x, d1 = v0.y, d2 = v0.z, d3 = v0.w;
    p4_stage_write(stg, 0, c0, relu4(d0, d1, d2, d3));

    float* my = ring[warp] + lane * 4;
#pragma unroll
    for (int i = 0; i < 16; i++) {               // element s = 1+i
        __pipeline_memcpy_async(my + i * 128, inp + (Ww - 2 - i) * Cc, 16);
        __pipeline_commit();
    }

#define P4_FLUSH(S0)                                                        \
    do {                                                                    \
        __syncwarp();                                                       \
        _Pragma("unroll")                                                   \
        for (int cb = 0; cb < 16; cb++) {                                   \
            const int c = cb * 8 + cq;                                      \
            const int pcf = c ^ (8 * tq);                                   \
            float4 val = make_float4(stg[(4 * tq + 0) * 128 + pcf],         \
                                     stg[(4 * tq + 1) * 128 + pcf],         \
                                     stg[(4 * tq + 2) * 128 + pcf],         \
                                     stg[(4 * tq + 3) * 128 + pcf]);        \
            __stcs((float4*)(obase + (size_t)c * (Hh * Ww) + (S0) + 4 * tq), val); \
        }                                                                   \
        __syncwarp();                                                       \
    } while (0)

    for (int s = 1; s + 1 < 160; s += 2) {
        __pipeline_wait_prior(14);
        float* sl0 = my + ((s - 1) & 15) * 128;
        float* sl1 = my + (s & 15) * 128;
        float4 cx0 = *(float4*)sl0;
        float4 cx1 = *(float4*)sl1;
        if (s + 16 < 160) __pipeline_memcpy_async(sl0, inp + (Ww - 1 - (s + 16)) * Cc, 16);
        __pipeline_commit();
        if (s + 17 < 160) __pipeline_memcpy_async(sl1, inp + (Ww - 1 - (s + 17)) * Cc, 16);
        __pipeline_commit();

        scan_step(d0, d1, d2, d3, cx0.x, cx0.y, cx0.z, cx0.w, wk, b, lane);
        p4_stage_write(stg, s & 15, c0, relu4(d0, d1, d2, d3));
        if ((s & 15) == 15) P4_FLUSH(s - 15);

        scan_step(d0, d1, d2, d3, cx1.x, cx1.y, cx1.z, cx1.w, wk, b, lane);
        p4_stage_write(stg, (s + 1) & 15, c0, relu4(d0, d1, d2, d3));
        if (((s + 1) & 15) == 15) P4_FLUSH(s - 14);
    }
    // s = 159
    __pipeline_wait_prior(0);
    {
        float4 cx = *(float4*)(my + ((159 - 1) & 15) * 128);
        scan_step(d0, d1, d2, d3, cx.x, cx.y, cx.z, cx.w, wk, b, lane);
        p4_stage_write(stg, 15, c0, relu4(d0, d1, d2, d3));
        P4_FLUSH(144);
    }
#undef P4_FLUSH
}

extern "C" void kernel_launch(void* const* d_in, const int* in_sizes, int n_in,
                              void* d_out, int out_size)
{
    (void)in_sizes; (void)n_in; (void)out_size;
    const float* x  = (const float*)d_in[0];
    const float* wd = (const float*)d_in[1];
    const float* bd = (const float*)d_in[2];
    const float* wu = (const float*)d_in[3];
    const float* bu = (const float*)d_in[4];
    const float* wl = (const float*)d_in[5];
    const float* bl = (const float*)d_in[6];
    const float* wr = (const float*)d_in[7];
    const float* br = (const float*)d_in[8];
    float* out = (float*)d_out;

    k_pass1<<<320, 128>>>(x, wd, bd);
    k_pass2<<<320, 128>>>(wu, bu);
    k_pass3<<<320, 128>>>(wl, bl);
    k_pass4<<<320, 128>>>(wr, br, out);
}